// round 14
// baseline (speedup 1.0000x reference)
#include <cuda_runtime.h>
#include <cstdint>
#include <cstddef>

// Fixed problem shapes
#define MROWS  8192           // B*S
#define INDIM  4096
#define OUTDIM 4096
#define RANK   8
#define NTHR   256            // 8 warps per CTA, 3 CTAs per SM (reg-capped)
#define TROWS  16             // rows per tile; warp owns 2 rows
#define NTILE  (MROWS/TROWS)  // 512
#define NC     32             // i-chunks of 128 floats (lane owns 4 i per chunk)

__constant__ float c_nf4[16] = {
    -1.0f, -0.6961928009986877f, -0.5250730514526367f, -0.39491748809814453f,
    -0.28444138169288635f, -0.18477343022823334f, -0.09105003625154495f, 0.0f,
    0.07958029955625534f, 0.16093020141124725f, 0.24611230194568634f,
    0.33791524171829224f, 0.44070982933044434f, 0.5626170039176941f,
    0.7229568362236328f, 1.0f};

// Pre-dequantized weights (scratch __device__ globals; L1/L2-resident)
__device__ __align__(16) float g_WA[RANK * INDIM];    // [r][i]
__device__ __align__(16) float g_WBt[RANK * OUTDIM];  // [r][o], pre-scaled by 4.0

// Single merged dequant kernel (one launch; proven)
__global__ void dequant_kernel(const int* __restrict__ codesA,
                               const float* __restrict__ absmaxA,
                               const int* __restrict__ codesB,
                               const float* __restrict__ absmaxB) {
    int i = blockIdx.x * blockDim.x + threadIdx.x;
    if (i < RANK * INDIM) {
        g_WA[i] = c_nf4[codesA[i] & 15] * absmaxA[i >> 6];
    } else {
        int j = i - RANK * INDIM;
        if (j < OUTDIM * RANK) {
            int o = j >> 3, r = j & 7;
            g_WBt[r * OUTDIM + o] = 4.0f * c_nf4[codesB[j] & 15] * absmaxB[j >> 6];
        }
    }
}

__device__ __forceinline__ void fma2(unsigned long long& d,
                                     unsigned long long a, unsigned long long b) {
    asm("fma.rn.f32x2 %0, %1, %2, %0;" : "+l"(d) : "l"(a), "l"(b));
}
__device__ __forceinline__ unsigned long long pk2(float v) {
    unsigned long long r; asm("mov.b64 %0, {%1, %1};" : "=l"(r) : "f"(v)); return r;
}
__device__ __forceinline__ unsigned long long pkab(float a, float b) {
    unsigned long long r; asm("mov.b64 %0, {%1, %2};" : "=l"(r) : "f"(a), "f"(b)); return r;
}
__device__ __forceinline__ float2 unpk(unsigned long long v) {
    float2 f; asm("mov.b64 {%0, %1}, %2;" : "=f"(f.x), "=f"(f.y) : "l"(v)); return f;
}
// 16B streaming load (evict-first: protect L1 for the weights)
__device__ __forceinline__ ulonglong2 ldcs16(const void* p) {
    ulonglong2 v;
    asm volatile("ld.global.cs.v2.u64 {%0, %1}, [%2];"
                 : "=l"(v.x), "=l"(v.y) : "l"(p));
    return v;
}
// 16B read-only cached load
__device__ __forceinline__ ulonglong2 ldg16(const void* p) {
    ulonglong2 v;
    asm volatile("ld.global.nc.v2.u64 {%0, %1}, [%2];"
                 : "=l"(v.x), "=l"(v.y) : "l"(p));
    return v;
}

__global__ void __launch_bounds__(NTHR, 3)
qlora_kernel(const float* __restrict__ x, float* __restrict__ out)
{
    __shared__ float sInt[TROWS * RANK];   // interm[row][r]
    const int tid = threadIdx.x, lane = tid & 31, wid = tid >> 5;
    const int tile = blockIdx.x;

    // ---- phase 1: warp owns rows 2*wid..+1; lane owns i = 4*lane + 128*c ----
    const char* xr0 = (const char*)(x + ((size_t)tile * TROWS + wid * 2) * INDIM
                                      + 4 * lane);
    const char* xr1 = xr0 + INDIM * 4;

    unsigned long long acc[2][RANK];
    #pragma unroll
    for (int m = 0; m < 2; m++)
        #pragma unroll
        for (int r = 0; r < RANK; r++) acc[m][r] = 0ull;

    const ulonglong2* __restrict__ wa = (const ulonglong2*)g_WA;  // [r][i/4] 16B units
    const int wl = lane;

    ulonglong2 xa[2], xb[2];
    xa[0] = ldcs16(xr0); xa[1] = ldcs16(xr1);

    #pragma unroll 1
    for (int c = 0; c < NC; c += 2) {
        // prefetch chunk c+1 (always valid: c <= 30)
        {
            int off = (c + 1) * 512;   // 128 floats = 512 B
            xb[0] = ldcs16(xr0 + off); xb[1] = ldcs16(xr1 + off);
        }
        // compute chunk c with xa
        #pragma unroll
        for (int r = 0; r < RANK; r++) {
            ulonglong2 wv = ldg16(wa + (size_t)r * (INDIM / 4) + c * 32 + wl);
            #pragma unroll
            for (int m = 0; m < 2; m++) {
                fma2(acc[m][r], xa[m].x, wv.x);
                fma2(acc[m][r], xa[m].y, wv.y);
            }
        }
        // prefetch chunk c+2 into xa (guarded at the tail)
        if (c + 2 < NC) {
            int off = (c + 2) * 512;
            xa[0] = ldcs16(xr0 + off); xa[1] = ldcs16(xr1 + off);
        }
        // compute chunk c+1 with xb
        #pragma unroll
        for (int r = 0; r < RANK; r++) {
            ulonglong2 wv = ldg16(wa + (size_t)r * (INDIM / 4) + (c + 1) * 32 + wl);
            #pragma unroll
            for (int m = 0; m < 2; m++) {
                fma2(acc[m][r], xb[m].x, wv.x);
                fma2(acc[m][r], xb[m].y, wv.y);
            }
        }
    }

    // ---- warp-local reduction: horizontal add + butterfly over 32 lanes ----
    #pragma unroll
    for (int m = 0; m < 2; m++) {
        float v[RANK];
        #pragma unroll
        for (int r = 0; r < RANK; r++) {
            float2 p = unpk(acc[m][r]);
            float s = p.x + p.y;
            s += __shfl_xor_sync(0xffffffffu, s, 16);
            s += __shfl_xor_sync(0xffffffffu, s, 8);
            s += __shfl_xor_sync(0xffffffffu, s, 4);
            s += __shfl_xor_sync(0xffffffffu, s, 2);
            s += __shfl_xor_sync(0xffffffffu, s, 1);
            v[r] = s;
        }
        if (lane == 0) {
            float4* dst = (float4*)(sInt + (wid * 2 + m) * RANK);
            dst[0] = make_float4(v[0], v[1], v[2], v[3]);
            dst[1] = make_float4(v[4], v[5], v[6], v[7]);
        }
    }
    __syncthreads();

    // ---- phase 2 epilogue: thread owns 4 float4 col groups ----
    {
        size_t outbase = (size_t)tile * TROWS * OUTDIM;
        const float4* gWB4 = (const float4*)g_WBt;
        #pragma unroll
        for (int og = 0; og < 4; og++) {
            int g = tid + og * NTHR;
            unsigned long long wb01[RANK], wb23[RANK];
            #pragma unroll
            for (int r = 0; r < RANK; r++) {
                float4 w = __ldg(gWB4 + r * (OUTDIM / 4) + g);
                wb01[r] = pkab(w.x, w.y);
                wb23[r] = pkab(w.z, w.w);
            }
            #pragma unroll 4
            for (int m = 0; m < TROWS; m++) {
                const float4* ip = (const float4*)sInt + m * 2;
                float4 s0 = ip[0], s1 = ip[1];   // broadcast LDS
                float sv[RANK] = { s0.x, s0.y, s0.z, s0.w,
                                   s1.x, s1.y, s1.z, s1.w };
                unsigned long long o01 = 0ull, o23 = 0ull;
                #pragma unroll
                for (int r = 0; r < RANK; r++) {
                    unsigned long long s2 = pk2(sv[r]);
                    fma2(o01, s2, wb01[r]);
                    fma2(o23, s2, wb23[r]);
                }
                ulonglong2 ov; ov.x = o01; ov.y = o23;
                *(ulonglong2*)(out + outbase + (size_t)m * OUTDIM + g * 4) = ov;
            }
        }
    }
}

extern "C" void kernel_launch(void* const* d_in, const int* in_sizes, int n_in,
                              void* d_out, int out_size) {
    const float* x        = (const float*)d_in[0];
    const int*   codes_A  = (const int*)d_in[1];
    const float* absmax_A = (const float*)d_in[2];
    const int*   codes_B  = (const int*)d_in[3];
    const float* absmax_B = (const float*)d_in[4];
    float*       out      = (float*)d_out;
    (void)in_sizes; (void)n_in; (void)out_size;

    // single dequant launch covering both A (32768) and B (32768)
    dequant_kernel<<<(2 * RANK * INDIM + 255) / 256, 256>>>(
        codes_A, absmax_A, codes_B, absmax_B);

    // one CTA per 16-row tile; 3 CTAs co-resident per SM
    qlora_kernel<<<NTILE, NTHR>>>(x, out);
}

// round 15
// speedup vs baseline: 1.2635x; 1.2635x over previous
#include <cuda_runtime.h>
#include <cstdint>
#include <cstddef>

// Fixed problem shapes
#define MROWS  8192           // B*S
#define INDIM  4096
#define OUTDIM 4096
#define RANK   8
#define NTHR   256            // 8 warps per CTA, 2 CTAs per SM
#define TROWS  32             // rows per tile; warp owns 4 rows
#define NTILE  (MROWS/TROWS)  // 256
#define NC     32             // i-chunks of 128 floats (lane owns 16B per row-chunk)
#define NBUF   5              // per-warp smem ring depth (4 chunks in flight)

#define WARP_BUF  (4*128)         // floats per (warp, buffer): 4 rows x 128
#define WARP_SMEM (NBUF*WARP_BUF) // 2560 floats = 10 KB per warp
#define S_X   0                   // 8 warps x 2560 = 20480 floats
#define S_INT (8*WARP_SMEM)       // interm[32][8]
#define S_TOT (S_INT + TROWS*RANK)
#define SMEM_BYTES (S_TOT*4)      // 82944 B (2 CTAs = 166 KB/SM)

__constant__ float c_nf4[16] = {
    -1.0f, -0.6961928009986877f, -0.5250730514526367f, -0.39491748809814453f,
    -0.28444138169288635f, -0.18477343022823334f, -0.09105003625154495f, 0.0f,
    0.07958029955625534f, 0.16093020141124725f, 0.24611230194568634f,
    0.33791524171829224f, 0.44070982933044434f, 0.5626170039176941f,
    0.7229568362236328f, 1.0f};

// Pre-dequantized weights (scratch __device__ globals; L1/L2-resident)
__device__ __align__(16) float g_WA[RANK * INDIM];    // [r][i]
__device__ __align__(16) float g_WBt[RANK * OUTDIM];  // [r][o], pre-scaled by 4.0

__global__ void dequant_kernel(const int* __restrict__ codesA,
                               const float* __restrict__ absmaxA,
                               const int* __restrict__ codesB,
                               const float* __restrict__ absmaxB) {
    int i = blockIdx.x * blockDim.x + threadIdx.x;
    if (i < RANK * INDIM) {
        g_WA[i] = c_nf4[codesA[i] & 15] * absmaxA[i >> 6];
    } else {
        int j = i - RANK * INDIM;
        if (j < OUTDIM * RANK) {
            int o = j >> 3, r = j & 7;
            g_WBt[r * OUTDIM + o] = 4.0f * c_nf4[codesB[j] & 15] * absmaxB[j >> 6];
        }
    }
}

__device__ __forceinline__ void cp_async16(uint32_t saddr, const void* gptr) {
    asm volatile("cp.async.cg.shared.global [%0], [%1], 16;\n"
                 :: "r"(saddr), "l"(gptr));
}
__device__ __forceinline__ void fma2(unsigned long long& d,
                                     unsigned long long a, unsigned long long b) {
    asm("fma.rn.f32x2 %0, %1, %2, %0;" : "+l"(d) : "l"(a), "l"(b));
}
__device__ __forceinline__ unsigned long long pk2(float v) {
    unsigned long long r; asm("mov.b64 %0, {%1, %1};" : "=l"(r) : "f"(v)); return r;
}
__device__ __forceinline__ unsigned long long pkab(float a, float b) {
    unsigned long long r; asm("mov.b64 %0, {%1, %2};" : "=l"(r) : "f"(a), "f"(b)); return r;
}
__device__ __forceinline__ float2 unpk(unsigned long long v) {
    float2 f; asm("mov.b64 {%0, %1}, %2;" : "=f"(f.x), "=f"(f.y) : "l"(v)); return f;
}
__device__ __forceinline__ ulonglong2 ldg16(const void* p) {
    ulonglong2 v;
    asm volatile("ld.global.nc.v2.u64 {%0, %1}, [%2];"
                 : "=l"(v.x), "=l"(v.y) : "l"(p));
    return v;
}

__global__ void __launch_bounds__(NTHR, 2)
qlora_kernel(const float* __restrict__ x, float* __restrict__ out)
{
    extern __shared__ float sm[];
    const int tid = threadIdx.x, lane = tid & 31, wid = tid >> 5;
    const int tile = blockIdx.x;

    // lane-private gmem source base: rows 4*wid..+3, byte slice [16*lane, +16)
    const float* src0 = x + ((size_t)tile * TROWS + wid * 4) * INDIM + 4 * lane;
    // lane-private smem base within this warp's ring
    const uint32_t smb = (uint32_t)__cvta_generic_to_shared(sm)
                       + (uint32_t)((wid * WARP_SMEM + lane * 4) * 4);
    float* smr = sm + wid * WARP_SMEM + lane * 4;

    // producer: 4 copies (one per row) of chunk c into ring slot bb
    auto produce = [&](int c, int bb) {
        uint32_t dst = smb + (uint32_t)(bb * WARP_BUF * 4);
        const float* s = src0 + c * 128;
        #pragma unroll
        for (int m = 0; m < 4; m++)
            cp_async16(dst + m * 128 * 4, s + (size_t)m * INDIM);
    };

    unsigned long long acc[4][RANK];
    #pragma unroll
    for (int m = 0; m < 4; m++)
        #pragma unroll
        for (int r = 0; r < RANK; r++) acc[m][r] = 0ull;

    // prologue: chunks 0..3 into slots 0..3 (one commit group each)
    #pragma unroll
    for (int c = 0; c < NBUF - 1; c++) {
        produce(c, c);
        asm volatile("cp.async.commit_group;\n" ::: "memory");
    }

    const ulonglong2* __restrict__ wa = (const ulonglong2*)g_WA;  // [r][i/4]
    int cbuf = 0;   // ring slot of chunk c
    int pbuf = NBUF - 1;

    #pragma unroll 1
    for (int c = 0; c < NC; c++) {
        asm volatile("cp.async.wait_group 3;\n" ::: "memory");
        // chunk c (this lane's own copies) is visible to this thread

        ulonglong2 xv[4];
        const float* rb = smr + cbuf * WARP_BUF;
        #pragma unroll
        for (int m = 0; m < 4; m++)
            xv[m] = *(const ulonglong2*)(rb + m * 128);   // conflict-free LDS.128

        // refill: chunk c+4 into slot (c-1)%5 (its readers retired last iter)
        if (c + NBUF - 1 < NC) produce(c + NBUF - 1, pbuf);
        asm volatile("cp.async.commit_group;\n" ::: "memory");
        pbuf = cbuf;
        cbuf = (cbuf + 1 == NBUF) ? 0 : cbuf + 1;

        // compute: 8 W loads (L1-resident, coalesced) + 64 fma2
        #pragma unroll
        for (int r = 0; r < RANK; r++) {
            ulonglong2 wv = ldg16(wa + (size_t)r * (INDIM / 4) + c * 32 + lane);
            #pragma unroll
            for (int m = 0; m < 4; m++) {
                fma2(acc[m][r], xv[m].x, wv.x);
                fma2(acc[m][r], xv[m].y, wv.y);
            }
        }
    }

    // ---- warp-local reduction: horizontal add + butterfly over 32 lanes ----
    float* sInt = sm + S_INT;
    #pragma unroll
    for (int m = 0; m < 4; m++) {
        float v[RANK];
        #pragma unroll
        for (int r = 0; r < RANK; r++) {
            float2 p = unpk(acc[m][r]);
            float s = p.x + p.y;
            s += __shfl_xor_sync(0xffffffffu, s, 16);
            s += __shfl_xor_sync(0xffffffffu, s, 8);
            s += __shfl_xor_sync(0xffffffffu, s, 4);
            s += __shfl_xor_sync(0xffffffffu, s, 2);
            s += __shfl_xor_sync(0xffffffffu, s, 1);
            v[r] = s;
        }
        if (lane == 0) {
            float4* dst = (float4*)(sInt + (wid * 4 + m) * RANK);
            dst[0] = make_float4(v[0], v[1], v[2], v[3]);
            dst[1] = make_float4(v[4], v[5], v[6], v[7]);
        }
    }
    __syncthreads();

    // ---- phase 2 epilogue: thread owns 4 float4 col groups ----
    {
        size_t outbase = (size_t)tile * TROWS * OUTDIM;
        const float4* gWB4 = (const float4*)g_WBt;
        #pragma unroll
        for (int og = 0; og < 4; og++) {
            int g = tid + og * NTHR;
            unsigned long long wb01[RANK], wb23[RANK];
            #pragma unroll
            for (int r = 0; r < RANK; r++) {
                float4 w = __ldg(gWB4 + r * (OUTDIM / 4) + g);
                wb01[r] = pkab(w.x, w.y);
                wb23[r] = pkab(w.z, w.w);
            }
            #pragma unroll 4
            for (int m = 0; m < TROWS; m++) {
                const float4* ip = (const float4*)sInt + m * 2;
                float4 s0 = ip[0], s1 = ip[1];   // broadcast LDS
                float sv[RANK] = { s0.x, s0.y, s0.z, s0.w,
                                   s1.x, s1.y, s1.z, s1.w };
                unsigned long long o01 = 0ull, o23 = 0ull;
                #pragma unroll
                for (int r = 0; r < RANK; r++) {
                    unsigned long long s2 = pk2(sv[r]);
                    fma2(o01, s2, wb01[r]);
                    fma2(o23, s2, wb23[r]);
                }
                ulonglong2 ov; ov.x = o01; ov.y = o23;
                *(ulonglong2*)(out + outbase + (size_t)m * OUTDIM + g * 4) = ov;
            }
        }
    }
}

extern "C" void kernel_launch(void* const* d_in, const int* in_sizes, int n_in,
                              void* d_out, int out_size) {
    const float* x        = (const float*)d_in[0];
    const int*   codes_A  = (const int*)d_in[1];
    const float* absmax_A = (const float*)d_in[2];
    const int*   codes_B  = (const int*)d_in[3];
    const float* absmax_B = (const float*)d_in[4];
    float*       out      = (float*)d_out;
    (void)in_sizes; (void)n_in; (void)out_size;

    // single dequant launch covering both A (32768) and B (32768)
    dequant_kernel<<<(2 * RANK * INDIM + 255) / 256, 256>>>(
        codes_A, absmax_A, codes_B, absmax_B);

    cudaFuncSetAttribute(qlora_kernel,
                         cudaFuncAttributeMaxDynamicSharedMemorySize, SMEM_BYTES);
    // one CTA per 32-row tile; 2 CTAs co-resident per SM; one wave
    qlora_kernel<<<NTILE, NTHR, SMEM_BYTES>>>(x, out);
}